// round 13
// baseline (speedup 1.0000x reference)
#include <cuda_runtime.h>

#define I_ 2049
#define J_ 2048
#define NITER 5
#define EPSV 1e-20f

#define GRID_I2 1025   // ceil(I_/2) blocks, 2 rows/block (4 warps: 2 rows x 2 halves)
#define GRID_J2 1024   // J_/2 blocks, 2 cols/block

// Scratch (device globals; no allocations allowed).
__device__ float4 g_Xc [(size_t)I_ * J_];   // [i][j] = (x0r,x0i,x1r,x1i)
__device__ float4 g_XcT[(size_t)J_ * I_];   // [j][i]
__device__ float4 g_Th[2][2][2][I_];        // [pingpong][n][half][i]  unit-stride float4
__device__ float4 g_Vh[2][2][2][J_];        // [pingpong][n][half][j]  unit-stride float4
__device__ __align__(16) float g_W[I_ * 8]; // [i][row r][col m][re/im]
__device__ float4 g_Wp4[2][I_];             // snapshot: [n][i] = row n of W(i)

__device__ __forceinline__ float wsum(float v) {
#pragma unroll
    for (int o = 16; o; o >>= 1) v += __shfl_down_sync(0xffffffffu, v, o);
    return v;
}

// ---------------------------------------------------------------------------
// Fused setup: zero output, build XcT from X (M,J,I,2), init T/V/W.
// ---------------------------------------------------------------------------
__global__ void k_setup_all(const float* __restrict__ X,
                            const float* __restrict__ T0,
                            const float* __restrict__ V0,
                            float* __restrict__ out, size_t nf) {
    size_t tid = (size_t)blockIdx.x * blockDim.x + threadIdx.x;
    if (tid < nf) out[tid] = 0.f;
    if (tid < (size_t)J_ * I_) {
        int j = (int)(tid / I_);
        int i = (int)(tid - (size_t)j * I_);
        size_t base0 = ((size_t)j * I_ + i) * 2;          // m=0
        size_t base1 = ((size_t)(J_ + j) * I_ + i) * 2;   // m=1
        g_XcT[tid] = make_float4(X[base0], X[base0 + 1], X[base1], X[base1 + 1]);
    }
    if (tid < I_) {
        int t = (int)tid;
#pragma unroll
        for (int n = 0; n < 2; n++) {
            float a[8];
#pragma unroll
            for (int k = 0; k < 8; k++) a[k] = T0[((size_t)t * 8 + k) * 2 + n];
            g_Th[0][n][0][t] = make_float4(a[0], a[1], a[2], a[3]);
            g_Th[0][n][1][t] = make_float4(a[4], a[5], a[6], a[7]);
        }
        float* w = &g_W[t * 8];
        w[0] = 1.f; w[1] = 0.f; w[2] = 0.f; w[3] = 0.f;
        w[4] = 0.f; w[5] = 0.f; w[6] = 1.f; w[7] = 0.f;  // W = eye(2)
    }
    if (tid < J_) {
        int t = (int)tid;
#pragma unroll
        for (int n = 0; n < 2; n++) {
            float a[8];
#pragma unroll
            for (int k = 0; k < 8; k++) a[k] = V0[((size_t)k * J_ + t) * 2 + n];
            g_Vh[0][n][0][t] = make_float4(a[0], a[1], a[2], a[3]);
            g_Vh[0][n][1][t] = make_float4(a[4], a[5], a[6], a[7]);
        }
    }
}

// Tiled transpose g_XcT -> g_Xc (both sides coalesced).
__global__ void k_build_x() {
    __shared__ float4 tile[32][33];
    const int i0 = blockIdx.x * 32, j0 = blockIdx.y * 32;
    for (int r = threadIdx.y; r < 32; r += 8) {
        int i = i0 + threadIdx.x, j = j0 + r;
        if (i < I_ && j < J_) tile[r][threadIdx.x] = g_XcT[(size_t)j * I_ + i];
    }
    __syncthreads();
    for (int r = threadIdx.y; r < 32; r += 8) {
        int i = i0 + r, j = j0 + threadIdx.x;
        if (i < I_ && j < J_) g_Xc[(size_t)i * J_ + j] = tile[threadIdx.x][r];
    }
}

// Fallback zero (only used when input validation fails).
__global__ void k_zero_out(float* __restrict__ out, size_t nf) {
    size_t tid = (size_t)blockIdx.x * blockDim.x + threadIdx.x;
    if (tid < nf) out[tid] = 0.f;
}

// ---------------------------------------------------------------------------
// T update core. 2 warps per row i: half h covers j in [h*1024,(h+1)*1024).
// snap: snapshot W rows -> Wp4 and use live W for Yn; else read Wp4.
// ---------------------------------------------------------------------------
__device__ __forceinline__ void updT_core(int i, int half, int lane,
                                          int pp, int n, int snap, float* sp) {
    const bool act = (i < I_);
    float4 wv = make_float4(0.f, 0.f, 0.f, 0.f);
    float tk[8];
#pragma unroll
    for (int k = 0; k < 8; k++) tk[k] = 0.f;
    if (act) {
        if (snap && half == 0 && lane == 0) {
            g_Wp4[0][i] = *(const float4*)&g_W[i * 8];
            g_Wp4[1][i] = *(const float4*)&g_W[i * 8 + 4];
        }
        wv = snap ? *(const float4*)&g_W[i * 8 + n * 4] : g_Wp4[n][i];
        float4 t0 = g_Th[pp][n][0][i];
        float4 t1 = g_Th[pp][n][1][i];
        tk[0] = t0.x; tk[1] = t0.y; tk[2] = t0.z; tk[3] = t0.w;
        tk[4] = t1.x; tk[5] = t1.y; tk[6] = t1.z; tk[7] = t1.w;
    }
    float acc[16];
#pragma unroll
    for (int k = 0; k < 16; k++) acc[k] = 0.f;
    if (act) {
        const float4* __restrict__ xrow = &g_Xc[(size_t)i * J_ + half * 1024];
        const float4* __restrict__ vA = &g_Vh[pp][n][0][half * 1024];
        const float4* __restrict__ vB = &g_Vh[pp][n][1][half * 1024];
#pragma unroll 4
        for (int jj = lane; jj < 1024; jj += 32) {
            float4 x = xrow[jj];
            float4 va = vA[jj];
            float4 vb = vB[jj];
            float ynr = wv.x * x.x - wv.y * x.y + wv.z * x.z - wv.w * x.w;
            float yni = wv.x * x.y + wv.y * x.x + wv.z * x.w + wv.w * x.z;
            float a2 = ynr * ynr + yni * yni;
            float v[8] = {va.x, va.y, va.z, va.w, vb.x, vb.y, vb.z, vb.w};
            float rn = 0.f;
#pragma unroll
            for (int k = 0; k < 8; k++) rn = fmaf(tk[k], v[k], rn);
            float p  = a2 / (rn * rn + EPSV);
            float rd = 1.0f / rn;
#pragma unroll
            for (int k = 0; k < 8; k++) {
                acc[k]     = fmaf(p,  v[k], acc[k]);
                acc[8 + k] = fmaf(rd, v[k], acc[8 + k]);
            }
        }
    }
#pragma unroll
    for (int k = 0; k < 16; k++) acc[k] = wsum(acc[k]);
    if (act && half == 1 && lane == 0) {
#pragma unroll
        for (int k = 0; k < 16; k++) sp[k] = acc[k];
    }
    __syncthreads();
    if (act && half == 0 && lane == 0) {
        float r[8];
#pragma unroll
        for (int k = 0; k < 8; k++)
            r[k] = tk[k] * sqrtf((acc[k] + sp[k]) / (acc[8 + k] + sp[8 + k]));
        g_Th[pp ^ 1][n][0][i] = make_float4(r[0], r[1], r[2], r[3]);
        g_Th[pp ^ 1][n][1][i] = make_float4(r[4], r[5], r[6], r[7]);
    }
}

__global__ void __launch_bounds__(128, 9) k_updT(int pp, int n, int snap) {
    __shared__ float sp[2][16];
    const int wid = threadIdx.x >> 5, lane = threadIdx.x & 31;
    const int i = blockIdx.x * 2 + (wid >> 1);
    updT_core(i, wid & 1, lane, pp, n, snap, sp[wid >> 1]);
}

// ---------------------------------------------------------------------------
// W update core. 2 warps per row. D = (Xc/Rn) Xc^T / J (complex symmetric,
// no conj); 2x2 solve (W@D) b = e_n in fp64; W[:,:,n] = b / sqrt(b^T D b).
// ---------------------------------------------------------------------------
struct cdbl { double r, i; };
__device__ __forceinline__ cdbl cmul(cdbl a, cdbl b) { return {a.r * b.r - a.i * b.i, a.r * b.i + a.i * b.r}; }
__device__ __forceinline__ cdbl cadd(cdbl a, cdbl b) { return {a.r + b.r, a.i + b.i}; }
__device__ __forceinline__ cdbl csub(cdbl a, cdbl b) { return {a.r - b.r, a.i - b.i}; }
__device__ __forceinline__ cdbl cneg(cdbl a) { return {-a.r, -a.i}; }
__device__ __forceinline__ cdbl cdiv(cdbl a, cdbl b) {
    double d = b.r * b.r + b.i * b.i;
    return {(a.r * b.r + a.i * b.i) / d, (a.i * b.r - a.r * b.i) / d};
}
__device__ __forceinline__ cdbl csqrt_(cdbl z) {
    double m = sqrt(z.r * z.r + z.i * z.i);
    double re = sqrt(0.5 * fmax(m + z.r, 0.0));
    double im = sqrt(0.5 * fmax(m - z.r, 0.0));
    if (z.i < 0.0) im = -im;
    return {re, im};
}

__device__ __forceinline__ void solve_col(float* w, const float* d6, int n) {
    const double invJ = 1.0 / (double)J_;
    cdbl D00{(double)d6[0] * invJ, (double)d6[1] * invJ};
    cdbl D01{(double)d6[2] * invJ, (double)d6[3] * invJ};
    cdbl D11{(double)d6[4] * invJ, (double)d6[5] * invJ};
    cdbl w00{w[0], w[1]}, w01{w[2], w[3]}, w10{w[4], w[5]}, w11{w[6], w[7]};
    cdbl WD00 = cadd(cmul(w00, D00), cmul(w01, D01));
    cdbl WD01 = cadd(cmul(w00, D01), cmul(w01, D11));
    cdbl WD10 = cadd(cmul(w10, D00), cmul(w11, D01));
    cdbl WD11 = cadd(cmul(w10, D01), cmul(w11, D11));
    cdbl det = csub(cmul(WD00, WD11), cmul(WD01, WD10));
    cdbl b0, b1;
    if (n == 0) { b0 = cdiv(WD11, det);       b1 = cdiv(cneg(WD10), det); }
    else        { b0 = cdiv(cneg(WD01), det); b1 = cdiv(WD00, det); }
    cdbl nrm = cadd(cadd(cmul(cmul(b0, b0), D00), cmul(cmul(b1, b1), D11)),
                    cmul(cdbl{2.0, 0.0}, cmul(cmul(b0, b1), D01)));
    cdbl sq = csqrt_(nrm);
    cdbl o0 = cdiv(b0, sq), o1 = cdiv(b1, sq);
    w[0 * 4 + n * 2 + 0] = (float)o0.r; w[0 * 4 + n * 2 + 1] = (float)o0.i;
    w[1 * 4 + n * 2 + 0] = (float)o1.r; w[1 * 4 + n * 2 + 1] = (float)o1.i;
}

__device__ __forceinline__ void updW_accum(int i, int half, int lane,
                                           int pp, int n, float* acc) {
#pragma unroll
    for (int k = 0; k < 6; k++) acc[k] = 0.f;
    float tk[8];
    {
        float4 t0 = g_Th[pp ^ 1][n][0][i];
        float4 t1 = g_Th[pp ^ 1][n][1][i];
        tk[0] = t0.x; tk[1] = t0.y; tk[2] = t0.z; tk[3] = t0.w;
        tk[4] = t1.x; tk[5] = t1.y; tk[6] = t1.z; tk[7] = t1.w;
    }
    const float4* __restrict__ xrow = &g_Xc[(size_t)i * J_ + half * 1024];
    const float4* __restrict__ vA = &g_Vh[pp ^ 1][n][0][half * 1024];
    const float4* __restrict__ vB = &g_Vh[pp ^ 1][n][1][half * 1024];
#pragma unroll 4
    for (int jj = lane; jj < 1024; jj += 32) {
        float4 x = xrow[jj];
        float4 va = vA[jj];
        float4 vb = vB[jj];
        float v[8] = {va.x, va.y, va.z, va.w, vb.x, vb.y, vb.z, vb.w};
        float rn = 0.f;
#pragma unroll
        for (int k = 0; k < 8; k++) rn = fmaf(tk[k], v[k], rn);
        float inv = 1.0f / rn;
        acc[0] = fmaf(x.x * x.x - x.y * x.y, inv, acc[0]);
        acc[1] = fmaf(2.f * x.x * x.y,       inv, acc[1]);
        acc[2] = fmaf(x.x * x.z - x.y * x.w, inv, acc[2]);
        acc[3] = fmaf(x.x * x.w + x.y * x.z, inv, acc[3]);
        acc[4] = fmaf(x.z * x.z - x.w * x.w, inv, acc[4]);
        acc[5] = fmaf(2.f * x.z * x.w,       inv, acc[5]);
    }
#pragma unroll
    for (int k = 0; k < 6; k++) acc[k] = wsum(acc[k]);
}

// W update for n=1 + (last iteration) fused Y writeout.
__global__ void __launch_bounds__(128, 9) k_updW1(int pp, int last,
                                                  float* __restrict__ out,
                                                  size_t nf, int mode) {
    __shared__ float sp[2][6];
    __shared__ __align__(16) float sw[2][8];
    const int wid = threadIdx.x >> 5, lane = threadIdx.x & 31;
    const int row = wid >> 1, half = wid & 1;
    const int i = blockIdx.x * 2 + row;
    const bool act = (i < I_);
    float acc[6];
    if (act) updW_accum(i, half, lane, pp, 1, acc);
    if (act && half == 1 && lane == 0) {
#pragma unroll
        for (int k = 0; k < 6; k++) sp[row][k] = acc[k];
    }
    __syncthreads();
    if (act && half == 0 && lane == 0) {
        float d6[6];
#pragma unroll
        for (int k = 0; k < 6; k++) d6[k] = acc[k] + sp[row][k];
        float w[8];
#pragma unroll
        for (int k = 0; k < 8; k++) w[k] = g_W[i * 8 + k];
        solve_col(w, d6, 1);
        *(float4*)&g_W[i * 8]     = make_float4(w[0], w[1], w[2], w[3]);
        *(float4*)&g_W[i * 8 + 4] = make_float4(w[4], w[5], w[6], w[7]);
#pragma unroll
        for (int k = 0; k < 8; k++) sw[row][k] = w[k];
    }
    if (last) {
        __syncthreads();
        if (act) {
            float4 wa = *(const float4*)&sw[row][0];
            float4 wb = *(const float4*)&sw[row][4];
            const float4* __restrict__ xrow = &g_Xc[(size_t)i * J_];
            for (int j = half * 32 + lane; j < J_; j += 64) {
                float4 x = xrow[j];
                float y0r = wa.x * x.x - wa.y * x.y + wa.z * x.z - wa.w * x.w;
                float y0i = wa.x * x.y + wa.y * x.x + wa.z * x.w + wa.w * x.z;
                float y1r = wb.x * x.x - wb.y * x.y + wb.z * x.z - wb.w * x.w;
                float y1i = wb.x * x.y + wb.y * x.x + wb.z * x.w + wb.w * x.z;
                if (mode == 0) {
                    size_t b0 = (((size_t)i * 2 + 0) * J_ + j) * 2;
                    size_t b1 = (((size_t)i * 2 + 1) * J_ + j) * 2;
                    if (b0 + 1 < nf) { out[b0] = y0r; out[b0 + 1] = y0i; }
                    if (b1 + 1 < nf) { out[b1] = y1r; out[b1 + 1] = y1i; }
                } else {
                    size_t b0 = ((size_t)i * 2 + 0) * J_ + j;
                    size_t b1 = ((size_t)i * 2 + 1) * J_ + j;
                    if (b0 < nf) out[b0] = y0r;
                    if (b1 < nf) out[b1] = y1r;
                }
            }
        }
    }
}

// Fused: W-update(n=0) and T-update(n=1) are independent — one grid.
__global__ void __launch_bounds__(128, 9) k_W0T1(int pp) {
    __shared__ float sp[2][16];
    const int wid = threadIdx.x >> 5, lane = threadIdx.x & 31;
    if (blockIdx.x < GRID_I2) {
        const int half = wid & 1, row = wid >> 1;
        const int i = blockIdx.x * 2 + row;
        const bool act = (i < I_);
        float acc[6];
        if (act) updW_accum(i, half, lane, pp, 0, acc);
        if (act && half == 1 && lane == 0) {
#pragma unroll
            for (int k = 0; k < 6; k++) sp[row][k] = acc[k];
        }
        __syncthreads();
        if (act && half == 0 && lane == 0) {
            float d6[6];
#pragma unroll
            for (int k = 0; k < 6; k++) d6[k] = acc[k] + sp[row][k];
            float w[8];
#pragma unroll
            for (int k = 0; k < 8; k++) w[k] = g_W[i * 8 + k];
            solve_col(w, d6, 0);
            *(float4*)&g_W[i * 8]     = make_float4(w[0], w[1], w[2], w[3]);
            *(float4*)&g_W[i * 8 + 4] = make_float4(w[4], w[5], w[6], w[7]);
        }
    } else {
        const int i = (blockIdx.x - GRID_I2) * 2 + (wid >> 1);
        updT_core(i, wid & 1, lane, pp, 1, 0, sp[wid >> 1]);
    }
}

// ---------------------------------------------------------------------------
// V update. 2 warps per column j: half h covers i = h*32+lane, step 64.
// Two-phase loads (to -> rn, then tn -> accumulate) to cut live registers.
// Accumulation order identical to R11.
// ---------------------------------------------------------------------------
__global__ void __launch_bounds__(128, 9) k_updV(int pp, int n) {
    __shared__ float sp[2][16];
    const int wid = threadIdx.x >> 5, lane = threadIdx.x & 31;
    const int half = wid & 1;
    const int j = blockIdx.x * 2 + (wid >> 1);
    float* spj = sp[wid >> 1];

    float4 voa = g_Vh[pp][n][0][j];
    float4 vob = g_Vh[pp][n][1][j];

    float accn[8], accd[8];
#pragma unroll
    for (int k = 0; k < 8; k++) { accn[k] = 0.f; accd[k] = 0.f; }

    const float4* __restrict__ toA = &g_Th[pp][n][0][0];
    const float4* __restrict__ toB = &g_Th[pp][n][1][0];
    const float4* __restrict__ tnA = &g_Th[pp ^ 1][n][0][0];
    const float4* __restrict__ tnB = &g_Th[pp ^ 1][n][1][0];
    const float4* __restrict__ wp  = &g_Wp4[n][0];
    const float4* __restrict__ xcol = &g_XcT[(size_t)j * I_];
#pragma unroll 2
    for (int i = half * 32 + lane; i < I_; i += 64) {
        // Phase 1: rn from old T (same fma chain order as before)
        float4 ta = toA[i], tb = toB[i];
        float rn = 0.f;
        rn = fmaf(ta.x, voa.x, rn); rn = fmaf(ta.y, voa.y, rn);
        rn = fmaf(ta.z, voa.z, rn); rn = fmaf(ta.w, voa.w, rn);
        rn = fmaf(tb.x, vob.x, rn); rn = fmaf(tb.y, vob.y, rn);
        rn = fmaf(tb.z, vob.z, rn); rn = fmaf(tb.w, vob.w, rn);
        float4 x = xcol[i];
        float4 w = wp[i];
        float ynr = w.x * x.x - w.y * x.y + w.z * x.z - w.w * x.w;
        float yni = w.x * x.y + w.y * x.x + w.z * x.w + w.w * x.z;
        float a2 = ynr * ynr + yni * yni;
        float p  = a2 / (rn * rn + EPSV);
        float rd = 1.0f / rn;
        // Phase 2: accumulate with new T (same per-k order as before)
        float4 tc = tnA[i], td = tnB[i];
        accn[0] = fmaf(tc.x, p, accn[0]); accd[0] = fmaf(tc.x, rd, accd[0]);
        accn[1] = fmaf(tc.y, p, accn[1]); accd[1] = fmaf(tc.y, rd, accd[1]);
        accn[2] = fmaf(tc.z, p, accn[2]); accd[2] = fmaf(tc.z, rd, accd[2]);
        accn[3] = fmaf(tc.w, p, accn[3]); accd[3] = fmaf(tc.w, rd, accd[3]);
        accn[4] = fmaf(td.x, p, accn[4]); accd[4] = fmaf(td.x, rd, accd[4]);
        accn[5] = fmaf(td.y, p, accn[5]); accd[5] = fmaf(td.y, rd, accd[5]);
        accn[6] = fmaf(td.z, p, accn[6]); accd[6] = fmaf(td.z, rd, accd[6]);
        accn[7] = fmaf(td.w, p, accn[7]); accd[7] = fmaf(td.w, rd, accd[7]);
    }
#pragma unroll
    for (int k = 0; k < 8; k++) { accn[k] = wsum(accn[k]); accd[k] = wsum(accd[k]); }
    if (half == 1 && lane == 0) {
#pragma unroll
        for (int k = 0; k < 8; k++) { spj[k] = accn[k]; spj[8 + k] = accd[k]; }
    }
    __syncthreads();
    if (half == 0 && lane == 0) {
        float vo[8] = {voa.x, voa.y, voa.z, voa.w, vob.x, vob.y, vob.z, vob.w};
        float r[8];
#pragma unroll
        for (int k = 0; k < 8; k++)
            r[k] = vo[k] * sqrtf((accn[k] + spj[k]) / (accd[k] + spj[8 + k]));
        g_Vh[pp ^ 1][n][0][j] = make_float4(r[0], r[1], r[2], r[3]);
        g_Vh[pp ^ 1][n][1][j] = make_float4(r[4], r[5], r[6], r[7]);
    }
}

// ---------------------------------------------------------------------------
extern "C" void kernel_launch(void* const* d_in, const int* in_sizes, int n_in,
                              void* d_out, int out_size) {
    float* out = (float*)d_out;
    const long long FULL = 16785408LL;   // I*N*J*2 floats (interleaved complex)
    const long long HALF = 8392704LL;    // I*N*J

    long long osz = out_size;
    size_t nf;
    int mode;
    if (osz >= FULL) { nf = (size_t)FULL; mode = 0; }
    else if (osz == HALF) { nf = (size_t)HALF; mode = 1; }
    else { nf = (size_t)(osz > 0 ? osz : 0); mode = 0; }

    // ---- Validate inputs BEFORE any kernel touches them ----
    bool valid = (n_in >= 3);
    int order[3] = {0, 1, 2};
    if (valid) {
        if ((long long)in_sizes[order[0]] < (long long)in_sizes[order[1]]) { int t = order[0]; order[0] = order[1]; order[1] = t; }
        if ((long long)in_sizes[order[1]] < (long long)in_sizes[order[2]]) { int t = order[1]; order[1] = order[2]; order[2] = t; }
        if ((long long)in_sizes[order[0]] < (long long)in_sizes[order[1]]) { int t = order[0]; order[0] = order[1]; order[1] = t; }
        long long s0 = in_sizes[order[0]], s1 = in_sizes[order[1]], s2 = in_sizes[order[2]];
        const long long EX = 16785408LL, ET = 32784LL, EV = 32768LL;
        bool ok_elems = (s0 == EX && s1 == ET && s2 == EV);
        bool ok_bytes = (s0 == EX * 4 && s1 == ET * 4 && s2 == EV * 4);
        valid = ok_elems || ok_bytes;
    }
    if (!valid) {
        if (nf > 0) k_zero_out<<<(int)((nf + 255) / 256), 256>>>(out, nf);
        return;
    }
    const float* X  = (const float*)d_in[order[0]];
    const float* T0 = (const float*)d_in[order[1]];
    const float* V0 = (const float*)d_in[order[2]];
    if (!X || !T0 || !V0) {
        if (nf > 0) k_zero_out<<<(int)((nf + 255) / 256), 256>>>(out, nf);
        return;
    }

    // ---- Setup (2 launches) ----
    size_t setup_n = nf > (size_t)I_ * J_ ? nf : (size_t)I_ * J_;
    k_setup_all<<<(int)((setup_n + 255) / 256), 256>>>(X, T0, V0, out, nf);
    k_build_x<<<dim3((I_ + 31) / 32, J_ / 32), dim3(32, 8)>>>();

    // ---- Iterations: updT(0), updV(0), [updW(0) || updT(1)], updV(1), updW(1)+out
    for (int it = 0; it < NITER; it++) {
        int pp = it & 1;
        k_updT<<<GRID_I2, 128>>>(pp, 0, 1);
        k_updV<<<GRID_J2, 128>>>(pp, 0);
        k_W0T1<<<2 * GRID_I2, 128>>>(pp);
        k_updV<<<GRID_J2, 128>>>(pp, 1);
        k_updW1<<<GRID_I2, 128>>>(pp, it == NITER - 1 ? 1 : 0, out, nf, mode);
    }
}

// round 14
// speedup vs baseline: 1.1957x; 1.1957x over previous
#include <cuda_runtime.h>

#define I_ 2049
#define J_ 2048
#define NITER 5
#define EPSV 1e-20f

// Scratch (device globals; no allocations allowed).
__device__ float4 g_Xc [(size_t)I_ * J_];   // [i][j] = (x0r,x0i,x1r,x1i)
__device__ float4 g_XcT[(size_t)J_ * I_];   // [j][i]
__device__ float4 g_Th[2][2][2][I_];        // [pingpong][n][half][i]  unit-stride float4
__device__ float4 g_Vh[2][2][2][J_];        // [pingpong][n][half][j]  unit-stride float4
__device__ __align__(16) float g_W[I_ * 8]; // [i][row r][col m][re/im]
__device__ float4 g_Wp4[2][I_];             // iteration-start W rows: [n][i]

__device__ __forceinline__ float wsum(float v) {
#pragma unroll
    for (int o = 16; o; o >>= 1) v += __shfl_down_sync(0xffffffffu, v, o);
    return v;
}

// ---------------------------------------------------------------------------
// Fused setup: zero output, build XcT from X (M,J,I,2), init T/V/W.
// ---------------------------------------------------------------------------
__global__ void k_setup_all(const float* __restrict__ X,
                            const float* __restrict__ T0,
                            const float* __restrict__ V0,
                            float* __restrict__ out, size_t nf) {
    size_t tid = (size_t)blockIdx.x * blockDim.x + threadIdx.x;
    if (tid < nf) out[tid] = 0.f;
    if (tid < (size_t)J_ * I_) {
        int j = (int)(tid / I_);
        int i = (int)(tid - (size_t)j * I_);
        size_t base0 = ((size_t)j * I_ + i) * 2;          // m=0
        size_t base1 = ((size_t)(J_ + j) * I_ + i) * 2;   // m=1
        g_XcT[tid] = make_float4(X[base0], X[base0 + 1], X[base1], X[base1 + 1]);
    }
    if (tid < I_) {
        int t = (int)tid;
#pragma unroll
        for (int n = 0; n < 2; n++) {
            float a[8];
#pragma unroll
            for (int k = 0; k < 8; k++) a[k] = T0[((size_t)t * 8 + k) * 2 + n];
            g_Th[0][n][0][t] = make_float4(a[0], a[1], a[2], a[3]);
            g_Th[0][n][1][t] = make_float4(a[4], a[5], a[6], a[7]);
        }
        float* w = &g_W[t * 8];
        w[0] = 1.f; w[1] = 0.f; w[2] = 0.f; w[3] = 0.f;
        w[4] = 0.f; w[5] = 0.f; w[6] = 1.f; w[7] = 0.f;  // W = eye(2)
    }
    if (tid < J_) {
        int t = (int)tid;
#pragma unroll
        for (int n = 0; n < 2; n++) {
            float a[8];
#pragma unroll
            for (int k = 0; k < 8; k++) a[k] = V0[((size_t)k * J_ + t) * 2 + n];
            g_Vh[0][n][0][t] = make_float4(a[0], a[1], a[2], a[3]);
            g_Vh[0][n][1][t] = make_float4(a[4], a[5], a[6], a[7]);
        }
    }
}

// Tiled transpose g_XcT -> g_Xc (both sides coalesced).
__global__ void k_build_x() {
    __shared__ float4 tile[32][33];
    const int i0 = blockIdx.x * 32, j0 = blockIdx.y * 32;
    for (int r = threadIdx.y; r < 32; r += 8) {
        int i = i0 + threadIdx.x, j = j0 + r;
        if (i < I_ && j < J_) tile[r][threadIdx.x] = g_XcT[(size_t)j * I_ + i];
    }
    __syncthreads();
    for (int r = threadIdx.y; r < 32; r += 8) {
        int i = i0 + r, j = j0 + threadIdx.x;
        if (i < I_ && j < J_) g_Xc[(size_t)i * J_ + j] = tile[threadIdx.x][r];
    }
}

// Fallback zero (only used when input validation fails).
__global__ void k_zero_out(float* __restrict__ out, size_t nf) {
    size_t tid = (size_t)blockIdx.x * blockDim.x + threadIdx.x;
    if (tid < nf) out[tid] = 0.f;
}

// ---------------------------------------------------------------------------
// T update, BOTH n per block. Block 128 = 4 warps: (n = wid>>1, half = wid&1),
// one row i = blockIdx.x. The two n-warps of each half read the same Xc lines
// (L1 sharing). Runs at iteration start: W is iteration-start (written only by
// updW2 later). n=0/half=0/lane=0 also mirrors W rows into g_Wp4 for updV2.
// Per-warp body identical to R11's updT_core.
// ---------------------------------------------------------------------------
__global__ void __launch_bounds__(128) k_updT2(int pp) {
    __shared__ float sp[2][16];
    const int wid = threadIdx.x >> 5, lane = threadIdx.x & 31;
    const int n = wid >> 1, half = wid & 1;
    const int i = blockIdx.x;

    if (n == 0 && half == 0 && lane == 0) {
        g_Wp4[0][i] = *(const float4*)&g_W[i * 8];
        g_Wp4[1][i] = *(const float4*)&g_W[i * 8 + 4];
    }
    float4 wv = *(const float4*)&g_W[i * 8 + n * 4];
    float4 t0 = g_Th[pp][n][0][i];
    float4 t1 = g_Th[pp][n][1][i];
    float tk[8] = {t0.x, t0.y, t0.z, t0.w, t1.x, t1.y, t1.z, t1.w};

    float acc[16];
#pragma unroll
    for (int k = 0; k < 16; k++) acc[k] = 0.f;
    {
        const float4* __restrict__ xrow = &g_Xc[(size_t)i * J_ + half * 1024];
        const float4* __restrict__ vA = &g_Vh[pp][n][0][half * 1024];
        const float4* __restrict__ vB = &g_Vh[pp][n][1][half * 1024];
#pragma unroll 4
        for (int jj = lane; jj < 1024; jj += 32) {
            float4 x = xrow[jj];
            float4 va = vA[jj];
            float4 vb = vB[jj];
            float ynr = wv.x * x.x - wv.y * x.y + wv.z * x.z - wv.w * x.w;
            float yni = wv.x * x.y + wv.y * x.x + wv.z * x.w + wv.w * x.z;
            float a2 = ynr * ynr + yni * yni;
            float v[8] = {va.x, va.y, va.z, va.w, vb.x, vb.y, vb.z, vb.w};
            float rn = 0.f;
#pragma unroll
            for (int k = 0; k < 8; k++) rn = fmaf(tk[k], v[k], rn);
            float p  = a2 / (rn * rn + EPSV);
            float rd = 1.0f / rn;
#pragma unroll
            for (int k = 0; k < 8; k++) {
                acc[k]     = fmaf(p,  v[k], acc[k]);
                acc[8 + k] = fmaf(rd, v[k], acc[8 + k]);
            }
        }
    }
#pragma unroll
    for (int k = 0; k < 16; k++) acc[k] = wsum(acc[k]);
    if (half == 1 && lane == 0) {
#pragma unroll
        for (int k = 0; k < 16; k++) sp[n][k] = acc[k];
    }
    __syncthreads();
    if (half == 0 && lane == 0) {
        float r[8];
#pragma unroll
        for (int k = 0; k < 8; k++)
            r[k] = tk[k] * sqrtf((acc[k] + sp[n][k]) / (acc[8 + k] + sp[n][8 + k]));
        g_Th[pp ^ 1][n][0][i] = make_float4(r[0], r[1], r[2], r[3]);
        g_Th[pp ^ 1][n][1][i] = make_float4(r[4], r[5], r[6], r[7]);
    }
}

// ---------------------------------------------------------------------------
// V update, BOTH n per block. Block 128 = 4 warps: (n, half), one column
// j = blockIdx.x. The two n-warps share XcT column lines. Uses OLD P/Rd
// (old T,V), NEW T weights, iteration-start W (g_Wp4). Per-warp body
// identical to R11's k_updV.
// ---------------------------------------------------------------------------
__global__ void __launch_bounds__(128) k_updV2(int pp) {
    __shared__ float sp[2][16];
    const int wid = threadIdx.x >> 5, lane = threadIdx.x & 31;
    const int n = wid >> 1, half = wid & 1;
    const int j = blockIdx.x;

    float4 voa = g_Vh[pp][n][0][j];
    float4 vob = g_Vh[pp][n][1][j];
    float vo[8] = {voa.x, voa.y, voa.z, voa.w, vob.x, vob.y, vob.z, vob.w};

    float accn[8], accd[8];
#pragma unroll
    for (int k = 0; k < 8; k++) { accn[k] = 0.f; accd[k] = 0.f; }

    const float4* __restrict__ toA = &g_Th[pp][n][0][0];
    const float4* __restrict__ toB = &g_Th[pp][n][1][0];
    const float4* __restrict__ tnA = &g_Th[pp ^ 1][n][0][0];
    const float4* __restrict__ tnB = &g_Th[pp ^ 1][n][1][0];
    const float4* __restrict__ wp  = &g_Wp4[n][0];
    const float4* __restrict__ xcol = &g_XcT[(size_t)j * I_];
#pragma unroll 2
    for (int i = half * 32 + lane; i < I_; i += 64) {
        float4 x  = xcol[i];
        float4 w  = wp[i];
        float4 ta = toA[i], tb = toB[i];
        float4 tc = tnA[i], td = tnB[i];
        float to[8] = {ta.x, ta.y, ta.z, ta.w, tb.x, tb.y, tb.z, tb.w};
        float tn[8] = {tc.x, tc.y, tc.z, tc.w, td.x, td.y, td.z, td.w};
        float ynr = w.x * x.x - w.y * x.y + w.z * x.z - w.w * x.w;
        float yni = w.x * x.y + w.y * x.x + w.z * x.w + w.w * x.z;
        float a2 = ynr * ynr + yni * yni;
        float rn = 0.f;
#pragma unroll
        for (int k = 0; k < 8; k++) rn = fmaf(to[k], vo[k], rn);
        float p  = a2 / (rn * rn + EPSV);
        float rd = 1.0f / rn;
#pragma unroll
        for (int k = 0; k < 8; k++) {
            accn[k] = fmaf(tn[k], p,  accn[k]);
            accd[k] = fmaf(tn[k], rd, accd[k]);
        }
    }
#pragma unroll
    for (int k = 0; k < 8; k++) { accn[k] = wsum(accn[k]); accd[k] = wsum(accd[k]); }
    if (half == 1 && lane == 0) {
#pragma unroll
        for (int k = 0; k < 8; k++) { sp[n][k] = accn[k]; sp[n][8 + k] = accd[k]; }
    }
    __syncthreads();
    if (half == 0 && lane == 0) {
        float r[8];
#pragma unroll
        for (int k = 0; k < 8; k++)
            r[k] = vo[k] * sqrtf((accn[k] + sp[n][k]) / (accd[k] + sp[n][8 + k]));
        g_Vh[pp ^ 1][n][0][j] = make_float4(r[0], r[1], r[2], r[3]);
        g_Vh[pp ^ 1][n][1][j] = make_float4(r[4], r[5], r[6], r[7]);
    }
}

// ---------------------------------------------------------------------------
// W update, BOTH n per block (fp64 2x2 solves done sequentially by thread 0,
// matching the reference's in-iteration column ordering). Block 128 = 4 warps
// (n, half), one row i = blockIdx.x; n-warps share Xc row lines.
// On the last iteration the block also writes Y = W_final @ Xc for its row.
// ---------------------------------------------------------------------------
struct cdbl { double r, i; };
__device__ __forceinline__ cdbl cmul(cdbl a, cdbl b) { return {a.r * b.r - a.i * b.i, a.r * b.i + a.i * b.r}; }
__device__ __forceinline__ cdbl cadd(cdbl a, cdbl b) { return {a.r + b.r, a.i + b.i}; }
__device__ __forceinline__ cdbl csub(cdbl a, cdbl b) { return {a.r - b.r, a.i - b.i}; }
__device__ __forceinline__ cdbl cneg(cdbl a) { return {-a.r, -a.i}; }
__device__ __forceinline__ cdbl cdiv(cdbl a, cdbl b) {
    double d = b.r * b.r + b.i * b.i;
    return {(a.r * b.r + a.i * b.i) / d, (a.i * b.r - a.r * b.i) / d};
}
__device__ __forceinline__ cdbl csqrt_(cdbl z) {
    double m = sqrt(z.r * z.r + z.i * z.i);
    double re = sqrt(0.5 * fmax(m + z.r, 0.0));
    double im = sqrt(0.5 * fmax(m - z.r, 0.0));
    if (z.i < 0.0) im = -im;
    return {re, im};
}

__device__ __forceinline__ void solve_col(float* w, const float* d6, int n) {
    const double invJ = 1.0 / (double)J_;
    cdbl D00{(double)d6[0] * invJ, (double)d6[1] * invJ};
    cdbl D01{(double)d6[2] * invJ, (double)d6[3] * invJ};
    cdbl D11{(double)d6[4] * invJ, (double)d6[5] * invJ};
    cdbl w00{w[0], w[1]}, w01{w[2], w[3]}, w10{w[4], w[5]}, w11{w[6], w[7]};
    cdbl WD00 = cadd(cmul(w00, D00), cmul(w01, D01));
    cdbl WD01 = cadd(cmul(w00, D01), cmul(w01, D11));
    cdbl WD10 = cadd(cmul(w10, D00), cmul(w11, D01));
    cdbl WD11 = cadd(cmul(w10, D01), cmul(w11, D11));
    cdbl det = csub(cmul(WD00, WD11), cmul(WD01, WD10));
    cdbl b0, b1;
    if (n == 0) { b0 = cdiv(WD11, det);       b1 = cdiv(cneg(WD10), det); }
    else        { b0 = cdiv(cneg(WD01), det); b1 = cdiv(WD00, det); }
    cdbl nrm = cadd(cadd(cmul(cmul(b0, b0), D00), cmul(cmul(b1, b1), D11)),
                    cmul(cdbl{2.0, 0.0}, cmul(cmul(b0, b1), D01)));
    cdbl sq = csqrt_(nrm);
    cdbl o0 = cdiv(b0, sq), o1 = cdiv(b1, sq);
    w[0 * 4 + n * 2 + 0] = (float)o0.r; w[0 * 4 + n * 2 + 1] = (float)o0.i;
    w[1 * 4 + n * 2 + 0] = (float)o1.r; w[1 * 4 + n * 2 + 1] = (float)o1.i;
}

__global__ void __launch_bounds__(128) k_updW2(int pp, int last,
                                               float* __restrict__ out,
                                               size_t nf, int mode) {
    __shared__ float spd[2][2][6];            // [n][half][6]
    __shared__ __align__(16) float sw[8];
    const int wid = threadIdx.x >> 5, lane = threadIdx.x & 31;
    const int n = wid >> 1, half = wid & 1;
    const int i = blockIdx.x;

    float4 t0 = g_Th[pp ^ 1][n][0][i];
    float4 t1 = g_Th[pp ^ 1][n][1][i];
    float tk[8] = {t0.x, t0.y, t0.z, t0.w, t1.x, t1.y, t1.z, t1.w};

    float acc[6];
#pragma unroll
    for (int k = 0; k < 6; k++) acc[k] = 0.f;
    {
        const float4* __restrict__ xrow = &g_Xc[(size_t)i * J_ + half * 1024];
        const float4* __restrict__ vA = &g_Vh[pp ^ 1][n][0][half * 1024];
        const float4* __restrict__ vB = &g_Vh[pp ^ 1][n][1][half * 1024];
#pragma unroll 4
        for (int jj = lane; jj < 1024; jj += 32) {
            float4 x = xrow[jj];
            float4 va = vA[jj];
            float4 vb = vB[jj];
            float v[8] = {va.x, va.y, va.z, va.w, vb.x, vb.y, vb.z, vb.w};
            float rn = 0.f;
#pragma unroll
            for (int k = 0; k < 8; k++) rn = fmaf(tk[k], v[k], rn);
            float inv = 1.0f / rn;
            acc[0] = fmaf(x.x * x.x - x.y * x.y, inv, acc[0]);
            acc[1] = fmaf(2.f * x.x * x.y,       inv, acc[1]);
            acc[2] = fmaf(x.x * x.z - x.y * x.w, inv, acc[2]);
            acc[3] = fmaf(x.x * x.w + x.y * x.z, inv, acc[3]);
            acc[4] = fmaf(x.z * x.z - x.w * x.w, inv, acc[4]);
            acc[5] = fmaf(2.f * x.z * x.w,       inv, acc[5]);
        }
    }
#pragma unroll
    for (int k = 0; k < 6; k++) acc[k] = wsum(acc[k]);
    if (lane == 0) {
#pragma unroll
        for (int k = 0; k < 6; k++) spd[n][half][k] = acc[k];
    }
    __syncthreads();
    if (threadIdx.x == 0) {
        float d6[6], w[8];
#pragma unroll
        for (int k = 0; k < 8; k++) w[k] = g_W[i * 8 + k];
#pragma unroll
        for (int k = 0; k < 6; k++) d6[k] = spd[0][0][k] + spd[0][1][k];
        solve_col(w, d6, 0);                  // updates col 0 of local w
#pragma unroll
        for (int k = 0; k < 6; k++) d6[k] = spd[1][0][k] + spd[1][1][k];
        solve_col(w, d6, 1);                  // uses updated w, updates col 1
        *(float4*)&g_W[i * 8]     = make_float4(w[0], w[1], w[2], w[3]);
        *(float4*)&g_W[i * 8 + 4] = make_float4(w[4], w[5], w[6], w[7]);
#pragma unroll
        for (int k = 0; k < 8; k++) sw[k] = w[k];
    }

    if (last) {
        __syncthreads();
        float4 wa = *(const float4*)&sw[0];
        float4 wb = *(const float4*)&sw[4];
        const float4* __restrict__ xrow = &g_Xc[(size_t)i * J_];
        for (int j = wid * 32 + lane; j < J_; j += 128) {
            float4 x = xrow[j];
            float y0r = wa.x * x.x - wa.y * x.y + wa.z * x.z - wa.w * x.w;
            float y0i = wa.x * x.y + wa.y * x.x + wa.z * x.w + wa.w * x.z;
            float y1r = wb.x * x.x - wb.y * x.y + wb.z * x.z - wb.w * x.w;
            float y1i = wb.x * x.y + wb.y * x.x + wb.z * x.w + wb.w * x.z;
            if (mode == 0) {
                size_t b0 = (((size_t)i * 2 + 0) * J_ + j) * 2;
                size_t b1 = (((size_t)i * 2 + 1) * J_ + j) * 2;
                if (b0 + 1 < nf) { out[b0] = y0r; out[b0 + 1] = y0i; }
                if (b1 + 1 < nf) { out[b1] = y1r; out[b1 + 1] = y1i; }
            } else {
                size_t b0 = ((size_t)i * 2 + 0) * J_ + j;
                size_t b1 = ((size_t)i * 2 + 1) * J_ + j;
                if (b0 < nf) out[b0] = y0r;
                if (b1 < nf) out[b1] = y1r;
            }
        }
    }
}

// ---------------------------------------------------------------------------
extern "C" void kernel_launch(void* const* d_in, const int* in_sizes, int n_in,
                              void* d_out, int out_size) {
    float* out = (float*)d_out;
    const long long FULL = 16785408LL;   // I*N*J*2 floats (interleaved complex)
    const long long HALF = 8392704LL;    // I*N*J

    long long osz = out_size;
    size_t nf;
    int mode;
    if (osz >= FULL) { nf = (size_t)FULL; mode = 0; }
    else if (osz == HALF) { nf = (size_t)HALF; mode = 1; }
    else { nf = (size_t)(osz > 0 ? osz : 0); mode = 0; }

    // ---- Validate inputs BEFORE any kernel touches them ----
    bool valid = (n_in >= 3);
    int order[3] = {0, 1, 2};
    if (valid) {
        if ((long long)in_sizes[order[0]] < (long long)in_sizes[order[1]]) { int t = order[0]; order[0] = order[1]; order[1] = t; }
        if ((long long)in_sizes[order[1]] < (long long)in_sizes[order[2]]) { int t = order[1]; order[1] = order[2]; order[2] = t; }
        if ((long long)in_sizes[order[0]] < (long long)in_sizes[order[1]]) { int t = order[0]; order[0] = order[1]; order[1] = t; }
        long long s0 = in_sizes[order[0]], s1 = in_sizes[order[1]], s2 = in_sizes[order[2]];
        const long long EX = 16785408LL, ET = 32784LL, EV = 32768LL;
        bool ok_elems = (s0 == EX && s1 == ET && s2 == EV);
        bool ok_bytes = (s0 == EX * 4 && s1 == ET * 4 && s2 == EV * 4);
        valid = ok_elems || ok_bytes;
    }
    if (!valid) {
        if (nf > 0) k_zero_out<<<(int)((nf + 255) / 256), 256>>>(out, nf);
        return;
    }
    const float* X  = (const float*)d_in[order[0]];
    const float* T0 = (const float*)d_in[order[1]];
    const float* V0 = (const float*)d_in[order[2]];
    if (!X || !T0 || !V0) {
        if (nf > 0) k_zero_out<<<(int)((nf + 255) / 256), 256>>>(out, nf);
        return;
    }

    // ---- Setup (2 launches) ----
    size_t setup_n = nf > (size_t)I_ * J_ ? nf : (size_t)I_ * J_;
    k_setup_all<<<(int)((setup_n + 255) / 256), 256>>>(X, T0, V0, out, nf);
    k_build_x<<<dim3((I_ + 31) / 32, J_ / 32), dim3(32, 8)>>>();

    // ---- Iterations: [T(0)||T(1)] -> [V(0)||V(1)] -> W(0),W(1) (+out) ----
    for (int it = 0; it < NITER; it++) {
        int pp = it & 1;
        k_updT2<<<I_, 128>>>(pp);
        k_updV2<<<J_, 128>>>(pp);
        k_updW2<<<I_, 128>>>(pp, it == NITER - 1 ? 1 : 0, out, nf, mode);
    }
}

// round 15
// speedup vs baseline: 1.2669x; 1.0595x over previous
#include <cuda_runtime.h>

#define I_ 2049
#define J_ 2048
#define NITER 5
#define EPSV 1e-20f

// Scratch (device globals; no allocations allowed).
__device__ float4 g_Xc [(size_t)I_ * J_];   // [i][j] = (x0r,x0i,x1r,x1i)
__device__ float4 g_XcT[(size_t)J_ * I_];   // [j][i]
__device__ float4 g_Th[2][2][2][I_];        // [pingpong][n][half][i]  unit-stride float4
__device__ float4 g_Vh[2][2][2][J_];        // [pingpong][n][half][j]  unit-stride float4
__device__ __align__(16) float g_W[I_ * 8]; // [i][row r][col m][re/im]
__device__ float4 g_Wp4[2][I_];             // iteration-start W rows: [n][i]

__device__ __forceinline__ float wsum(float v) {
#pragma unroll
    for (int o = 16; o; o >>= 1) v += __shfl_down_sync(0xffffffffu, v, o);
    return v;
}

// ---------------------------------------------------------------------------
// Fused setup: zero output, build XcT from X (M,J,I,2), init T/V/W.
// ---------------------------------------------------------------------------
__global__ void k_setup_all(const float* __restrict__ X,
                            const float* __restrict__ T0,
                            const float* __restrict__ V0,
                            float* __restrict__ out, size_t nf) {
    size_t tid = (size_t)blockIdx.x * blockDim.x + threadIdx.x;
    if (tid < nf) out[tid] = 0.f;
    if (tid < (size_t)J_ * I_) {
        int j = (int)(tid / I_);
        int i = (int)(tid - (size_t)j * I_);
        size_t base0 = ((size_t)j * I_ + i) * 2;          // m=0
        size_t base1 = ((size_t)(J_ + j) * I_ + i) * 2;   // m=1
        g_XcT[tid] = make_float4(X[base0], X[base0 + 1], X[base1], X[base1 + 1]);
    }
    if (tid < I_) {
        int t = (int)tid;
#pragma unroll
        for (int n = 0; n < 2; n++) {
            float a[8];
#pragma unroll
            for (int k = 0; k < 8; k++) a[k] = T0[((size_t)t * 8 + k) * 2 + n];
            g_Th[0][n][0][t] = make_float4(a[0], a[1], a[2], a[3]);
            g_Th[0][n][1][t] = make_float4(a[4], a[5], a[6], a[7]);
        }
        float* w = &g_W[t * 8];
        w[0] = 1.f; w[1] = 0.f; w[2] = 0.f; w[3] = 0.f;
        w[4] = 0.f; w[5] = 0.f; w[6] = 1.f; w[7] = 0.f;  // W = eye(2)
    }
    if (tid < J_) {
        int t = (int)tid;
#pragma unroll
        for (int n = 0; n < 2; n++) {
            float a[8];
#pragma unroll
            for (int k = 0; k < 8; k++) a[k] = V0[((size_t)k * J_ + t) * 2 + n];
            g_Vh[0][n][0][t] = make_float4(a[0], a[1], a[2], a[3]);
            g_Vh[0][n][1][t] = make_float4(a[4], a[5], a[6], a[7]);
        }
    }
}

// Tiled transpose g_XcT -> g_Xc (both sides coalesced).
__global__ void k_build_x() {
    __shared__ float4 tile[32][33];
    const int i0 = blockIdx.x * 32, j0 = blockIdx.y * 32;
    for (int r = threadIdx.y; r < 32; r += 8) {
        int i = i0 + threadIdx.x, j = j0 + r;
        if (i < I_ && j < J_) tile[r][threadIdx.x] = g_XcT[(size_t)j * I_ + i];
    }
    __syncthreads();
    for (int r = threadIdx.y; r < 32; r += 8) {
        int i = i0 + r, j = j0 + threadIdx.x;
        if (i < I_ && j < J_) g_Xc[(size_t)i * J_ + j] = tile[threadIdx.x][r];
    }
}

// Fallback zero (only used when input validation fails).
__global__ void k_zero_out(float* __restrict__ out, size_t nf) {
    size_t tid = (size_t)blockIdx.x * blockDim.x + threadIdx.x;
    if (tid < nf) out[tid] = 0.f;
}

// ---------------------------------------------------------------------------
// T update body for row i, given this row's iteration-start W rows in wv.
// Warp = (n, half). Reads g_Th[ppT][n], g_Vh[ppT][n]; writes g_Th[ppT^1][n].
// Identical FMA/reduction ordering to R14's k_updT2.
// ---------------------------------------------------------------------------
__device__ __forceinline__ void T_body(int i, int n, int half, int lane,
                                       int ppT, float4 wv, float* spn) {
    float4 t0 = g_Th[ppT][n][0][i];
    float4 t1 = g_Th[ppT][n][1][i];
    float tk[8] = {t0.x, t0.y, t0.z, t0.w, t1.x, t1.y, t1.z, t1.w};

    float acc[16];
#pragma unroll
    for (int k = 0; k < 16; k++) acc[k] = 0.f;
    {
        const float4* __restrict__ xrow = &g_Xc[(size_t)i * J_ + half * 1024];
        const float4* __restrict__ vA = &g_Vh[ppT][n][0][half * 1024];
        const float4* __restrict__ vB = &g_Vh[ppT][n][1][half * 1024];
#pragma unroll 4
        for (int jj = lane; jj < 1024; jj += 32) {
            float4 x = xrow[jj];
            float4 va = vA[jj];
            float4 vb = vB[jj];
            float ynr = wv.x * x.x - wv.y * x.y + wv.z * x.z - wv.w * x.w;
            float yni = wv.x * x.y + wv.y * x.x + wv.z * x.w + wv.w * x.z;
            float a2 = ynr * ynr + yni * yni;
            float v[8] = {va.x, va.y, va.z, va.w, vb.x, vb.y, vb.z, vb.w};
            float rn = 0.f;
#pragma unroll
            for (int k = 0; k < 8; k++) rn = fmaf(tk[k], v[k], rn);
            float p  = a2 / (rn * rn + EPSV);
            float rd = 1.0f / rn;
#pragma unroll
            for (int k = 0; k < 8; k++) {
                acc[k]     = fmaf(p,  v[k], acc[k]);
                acc[8 + k] = fmaf(rd, v[k], acc[8 + k]);
            }
        }
    }
#pragma unroll
    for (int k = 0; k < 16; k++) acc[k] = wsum(acc[k]);
    if (half == 1 && lane == 0) {
#pragma unroll
        for (int k = 0; k < 16; k++) spn[k] = acc[k];
    }
    __syncthreads();
    if (half == 0 && lane == 0) {
        float r[8];
#pragma unroll
        for (int k = 0; k < 8; k++)
            r[k] = tk[k] * sqrtf((acc[k] + spn[k]) / (acc[8 + k] + spn[8 + k]));
        g_Th[ppT ^ 1][n][0][i] = make_float4(r[0], r[1], r[2], r[3]);
        g_Th[ppT ^ 1][n][1][i] = make_float4(r[4], r[5], r[6], r[7]);
    }
}

// Standalone T update (iteration 0 only): uses live g_W, mirrors it to Wp4.
__global__ void __launch_bounds__(128) k_updT2(int pp) {
    __shared__ float sp[2][16];
    const int wid = threadIdx.x >> 5, lane = threadIdx.x & 31;
    const int n = wid >> 1, half = wid & 1;
    const int i = blockIdx.x;
    if (n == 0 && half == 0 && lane == 0) {
        g_Wp4[0][i] = *(const float4*)&g_W[i * 8];
        g_Wp4[1][i] = *(const float4*)&g_W[i * 8 + 4];
    }
    float4 wv = *(const float4*)&g_W[i * 8 + n * 4];
    T_body(i, n, half, lane, pp, wv, sp[n]);
}

// ---------------------------------------------------------------------------
// V update, BOTH n per block (unchanged from R14). Block 128 = 4 warps (n,
// half), one column j = blockIdx.x. Uses OLD P/Rd (old T,V), NEW T weights,
// iteration-start W (g_Wp4).
// ---------------------------------------------------------------------------
__global__ void __launch_bounds__(128) k_updV2(int pp) {
    __shared__ float sp[2][16];
    const int wid = threadIdx.x >> 5, lane = threadIdx.x & 31;
    const int n = wid >> 1, half = wid & 1;
    const int j = blockIdx.x;

    float4 voa = g_Vh[pp][n][0][j];
    float4 vob = g_Vh[pp][n][1][j];
    float vo[8] = {voa.x, voa.y, voa.z, voa.w, vob.x, vob.y, vob.z, vob.w};

    float accn[8], accd[8];
#pragma unroll
    for (int k = 0; k < 8; k++) { accn[k] = 0.f; accd[k] = 0.f; }

    const float4* __restrict__ toA = &g_Th[pp][n][0][0];
    const float4* __restrict__ toB = &g_Th[pp][n][1][0];
    const float4* __restrict__ tnA = &g_Th[pp ^ 1][n][0][0];
    const float4* __restrict__ tnB = &g_Th[pp ^ 1][n][1][0];
    const float4* __restrict__ wp  = &g_Wp4[n][0];
    const float4* __restrict__ xcol = &g_XcT[(size_t)j * I_];
#pragma unroll 2
    for (int i = half * 32 + lane; i < I_; i += 64) {
        float4 x  = xcol[i];
        float4 w  = wp[i];
        float4 ta = toA[i], tb = toB[i];
        float4 tc = tnA[i], td = tnB[i];
        float to[8] = {ta.x, ta.y, ta.z, ta.w, tb.x, tb.y, tb.z, tb.w};
        float tn[8] = {tc.x, tc.y, tc.z, tc.w, td.x, td.y, td.z, td.w};
        float ynr = w.x * x.x - w.y * x.y + w.z * x.z - w.w * x.w;
        float yni = w.x * x.y + w.y * x.x + w.z * x.w + w.w * x.z;
        float a2 = ynr * ynr + yni * yni;
        float rn = 0.f;
#pragma unroll
        for (int k = 0; k < 8; k++) rn = fmaf(to[k], vo[k], rn);
        float p  = a2 / (rn * rn + EPSV);
        float rd = 1.0f / rn;
#pragma unroll
        for (int k = 0; k < 8; k++) {
            accn[k] = fmaf(tn[k], p,  accn[k]);
            accd[k] = fmaf(tn[k], rd, accd[k]);
        }
    }
#pragma unroll
    for (int k = 0; k < 8; k++) { accn[k] = wsum(accn[k]); accd[k] = wsum(accd[k]); }
    if (half == 1 && lane == 0) {
#pragma unroll
        for (int k = 0; k < 8; k++) { sp[n][k] = accn[k]; sp[n][8 + k] = accd[k]; }
    }
    __syncthreads();
    if (half == 0 && lane == 0) {
        float r[8];
#pragma unroll
        for (int k = 0; k < 8; k++)
            r[k] = vo[k] * sqrtf((accn[k] + sp[n][k]) / (accd[k] + sp[n][8 + k]));
        g_Vh[pp ^ 1][n][0][j] = make_float4(r[0], r[1], r[2], r[3]);
        g_Vh[pp ^ 1][n][1][j] = make_float4(r[4], r[5], r[6], r[7]);
    }
}

// ---------------------------------------------------------------------------
// Complex fp64 helpers + sequential 2x2 column solve (reference ordering).
// ---------------------------------------------------------------------------
struct cdbl { double r, i; };
__device__ __forceinline__ cdbl cmul(cdbl a, cdbl b) { return {a.r * b.r - a.i * b.i, a.r * b.i + a.i * b.r}; }
__device__ __forceinline__ cdbl cadd(cdbl a, cdbl b) { return {a.r + b.r, a.i + b.i}; }
__device__ __forceinline__ cdbl csub(cdbl a, cdbl b) { return {a.r - b.r, a.i - b.i}; }
__device__ __forceinline__ cdbl cneg(cdbl a) { return {-a.r, -a.i}; }
__device__ __forceinline__ cdbl cdiv(cdbl a, cdbl b) {
    double d = b.r * b.r + b.i * b.i;
    return {(a.r * b.r + a.i * b.i) / d, (a.i * b.r - a.r * b.i) / d};
}
__device__ __forceinline__ cdbl csqrt_(cdbl z) {
    double m = sqrt(z.r * z.r + z.i * z.i);
    double re = sqrt(0.5 * fmax(m + z.r, 0.0));
    double im = sqrt(0.5 * fmax(m - z.r, 0.0));
    if (z.i < 0.0) im = -im;
    return {re, im};
}

__device__ __forceinline__ void solve_col(float* w, const float* d6, int n) {
    const double invJ = 1.0 / (double)J_;
    cdbl D00{(double)d6[0] * invJ, (double)d6[1] * invJ};
    cdbl D01{(double)d6[2] * invJ, (double)d6[3] * invJ};
    cdbl D11{(double)d6[4] * invJ, (double)d6[5] * invJ};
    cdbl w00{w[0], w[1]}, w01{w[2], w[3]}, w10{w[4], w[5]}, w11{w[6], w[7]};
    cdbl WD00 = cadd(cmul(w00, D00), cmul(w01, D01));
    cdbl WD01 = cadd(cmul(w00, D01), cmul(w01, D11));
    cdbl WD10 = cadd(cmul(w10, D00), cmul(w11, D01));
    cdbl WD11 = cadd(cmul(w10, D01), cmul(w11, D11));
    cdbl det = csub(cmul(WD00, WD11), cmul(WD01, WD10));
    cdbl b0, b1;
    if (n == 0) { b0 = cdiv(WD11, det);       b1 = cdiv(cneg(WD10), det); }
    else        { b0 = cdiv(cneg(WD01), det); b1 = cdiv(WD00, det); }
    cdbl nrm = cadd(cadd(cmul(cmul(b0, b0), D00), cmul(cmul(b1, b1), D11)),
                    cmul(cdbl{2.0, 0.0}, cmul(cmul(b0, b1), D01)));
    cdbl sq = csqrt_(nrm);
    cdbl o0 = cdiv(b0, sq), o1 = cdiv(b1, sq);
    w[0 * 4 + n * 2 + 0] = (float)o0.r; w[0 * 4 + n * 2 + 1] = (float)o0.i;
    w[1 * 4 + n * 2 + 0] = (float)o1.r; w[1 * 4 + n * 2 + 1] = (float)o1.i;
}

// ---------------------------------------------------------------------------
// Fused kernel: W update of iteration `pp` (both n, sequential solves) THEN
// T update of the NEXT iteration (ppT = pp^1) on the same (L1-hot) Xc row,
// using the freshly solved W from smem. doT=0 on the last iteration; last=1
// additionally writes Y = W_final @ Xc.
// ---------------------------------------------------------------------------
__global__ void __launch_bounds__(128) k_WT(int pp, int doT, int last,
                                            float* __restrict__ out,
                                            size_t nf, int mode) {
    __shared__ float spd[2][2][6];            // [n][half][6]
    __shared__ float spt[2][16];              // T-phase cross-half combine
    __shared__ __align__(16) float sw[8];
    const int wid = threadIdx.x >> 5, lane = threadIdx.x & 31;
    const int n = wid >> 1, half = wid & 1;
    const int i = blockIdx.x;

    // ---- W phase: accumulate D(n) over this row's j-half ----
    {
        float4 t0 = g_Th[pp ^ 1][n][0][i];
        float4 t1 = g_Th[pp ^ 1][n][1][i];
        float tk[8] = {t0.x, t0.y, t0.z, t0.w, t1.x, t1.y, t1.z, t1.w};
        float acc[6];
#pragma unroll
        for (int k = 0; k < 6; k++) acc[k] = 0.f;
        const float4* __restrict__ xrow = &g_Xc[(size_t)i * J_ + half * 1024];
        const float4* __restrict__ vA = &g_Vh[pp ^ 1][n][0][half * 1024];
        const float4* __restrict__ vB = &g_Vh[pp ^ 1][n][1][half * 1024];
#pragma unroll 4
        for (int jj = lane; jj < 1024; jj += 32) {
            float4 x = xrow[jj];
            float4 va = vA[jj];
            float4 vb = vB[jj];
            float v[8] = {va.x, va.y, va.z, va.w, vb.x, vb.y, vb.z, vb.w};
            float rn = 0.f;
#pragma unroll
            for (int k = 0; k < 8; k++) rn = fmaf(tk[k], v[k], rn);
            float inv = 1.0f / rn;
            acc[0] = fmaf(x.x * x.x - x.y * x.y, inv, acc[0]);
            acc[1] = fmaf(2.f * x.x * x.y,       inv, acc[1]);
            acc[2] = fmaf(x.x * x.z - x.y * x.w, inv, acc[2]);
            acc[3] = fmaf(x.x * x.w + x.y * x.z, inv, acc[3]);
            acc[4] = fmaf(x.z * x.z - x.w * x.w, inv, acc[4]);
            acc[5] = fmaf(2.f * x.z * x.w,       inv, acc[5]);
        }
#pragma unroll
        for (int k = 0; k < 6; k++) acc[k] = wsum(acc[k]);
        if (lane == 0) {
#pragma unroll
            for (int k = 0; k < 6; k++) spd[n][half][k] = acc[k];
        }
    }
    __syncthreads();
    if (threadIdx.x == 0) {
        float d6[6], w[8];
#pragma unroll
        for (int k = 0; k < 8; k++) w[k] = g_W[i * 8 + k];
#pragma unroll
        for (int k = 0; k < 6; k++) d6[k] = spd[0][0][k] + spd[0][1][k];
        solve_col(w, d6, 0);                  // updates col 0 of local w
#pragma unroll
        for (int k = 0; k < 6; k++) d6[k] = spd[1][0][k] + spd[1][1][k];
        solve_col(w, d6, 1);                  // uses updated w, updates col 1
        *(float4*)&g_W[i * 8]     = make_float4(w[0], w[1], w[2], w[3]);
        *(float4*)&g_W[i * 8 + 4] = make_float4(w[4], w[5], w[6], w[7]);
        g_Wp4[0][i] = make_float4(w[0], w[1], w[2], w[3]);   // iteration-start W
        g_Wp4[1][i] = make_float4(w[4], w[5], w[6], w[7]);   // for next V update
#pragma unroll
        for (int k = 0; k < 8; k++) sw[k] = w[k];
    }
    __syncthreads();

    if (doT) {
        // ---- T phase of the NEXT iteration (ppT = pp^1), W from smem ----
        float4 wv = *(const float4*)&sw[n * 4];
        T_body(i, n, half, lane, pp ^ 1, wv, spt[n]);
    }

    if (last) {
        // ---- Final Y = W_final @ Xc for this row ----
        float4 wa = *(const float4*)&sw[0];
        float4 wb = *(const float4*)&sw[4];
        const float4* __restrict__ xrow = &g_Xc[(size_t)i * J_];
        for (int j = wid * 32 + lane; j < J_; j += 128) {
            float4 x = xrow[j];
            float y0r = wa.x * x.x - wa.y * x.y + wa.z * x.z - wa.w * x.w;
            float y0i = wa.x * x.y + wa.y * x.x + wa.z * x.w + wa.w * x.z;
            float y1r = wb.x * x.x - wb.y * x.y + wb.z * x.z - wb.w * x.w;
            float y1i = wb.x * x.y + wb.y * x.x + wb.z * x.w + wb.w * x.z;
            if (mode == 0) {
                size_t b0 = (((size_t)i * 2 + 0) * J_ + j) * 2;
                size_t b1 = (((size_t)i * 2 + 1) * J_ + j) * 2;
                if (b0 + 1 < nf) { out[b0] = y0r; out[b0 + 1] = y0i; }
                if (b1 + 1 < nf) { out[b1] = y1r; out[b1 + 1] = y1i; }
            } else {
                size_t b0 = ((size_t)i * 2 + 0) * J_ + j;
                size_t b1 = ((size_t)i * 2 + 1) * J_ + j;
                if (b0 < nf) out[b0] = y0r;
                if (b1 < nf) out[b1] = y1r;
            }
        }
    }
}

// ---------------------------------------------------------------------------
extern "C" void kernel_launch(void* const* d_in, const int* in_sizes, int n_in,
                              void* d_out, int out_size) {
    float* out = (float*)d_out;
    const long long FULL = 16785408LL;   // I*N*J*2 floats (interleaved complex)
    const long long HALF = 8392704LL;    // I*N*J

    long long osz = out_size;
    size_t nf;
    int mode;
    if (osz >= FULL) { nf = (size_t)FULL; mode = 0; }
    else if (osz == HALF) { nf = (size_t)HALF; mode = 1; }
    else { nf = (size_t)(osz > 0 ? osz : 0); mode = 0; }

    // ---- Validate inputs BEFORE any kernel touches them ----
    bool valid = (n_in >= 3);
    int order[3] = {0, 1, 2};
    if (valid) {
        if ((long long)in_sizes[order[0]] < (long long)in_sizes[order[1]]) { int t = order[0]; order[0] = order[1]; order[1] = t; }
        if ((long long)in_sizes[order[1]] < (long long)in_sizes[order[2]]) { int t = order[1]; order[1] = order[2]; order[2] = t; }
        if ((long long)in_sizes[order[0]] < (long long)in_sizes[order[1]]) { int t = order[0]; order[0] = order[1]; order[1] = t; }
        long long s0 = in_sizes[order[0]], s1 = in_sizes[order[1]], s2 = in_sizes[order[2]];
        const long long EX = 16785408LL, ET = 32784LL, EV = 32768LL;
        bool ok_elems = (s0 == EX && s1 == ET && s2 == EV);
        bool ok_bytes = (s0 == EX * 4 && s1 == ET * 4 && s2 == EV * 4);
        valid = ok_elems || ok_bytes;
    }
    if (!valid) {
        if (nf > 0) k_zero_out<<<(int)((nf + 255) / 256), 256>>>(out, nf);
        return;
    }
    const float* X  = (const float*)d_in[order[0]];
    const float* T0 = (const float*)d_in[order[1]];
    const float* V0 = (const float*)d_in[order[2]];
    if (!X || !T0 || !V0) {
        if (nf > 0) k_zero_out<<<(int)((nf + 255) / 256), 256>>>(out, nf);
        return;
    }

    // ---- Setup (2 launches) ----
    size_t setup_n = nf > (size_t)I_ * J_ ? nf : (size_t)I_ * J_;
    k_setup_all<<<(int)((setup_n + 255) / 256), 256>>>(X, T0, V0, out, nf);
    k_build_x<<<dim3((I_ + 31) / 32, J_ / 32), dim3(32, 8)>>>();

    // ---- Iterations ----
    // it=0 T standalone; then per it: V2(it) -> [W(it) + T(it+1)] fused.
    k_updT2<<<I_, 128>>>(0);
    for (int it = 0; it < NITER; it++) {
        int pp = it & 1;
        k_updV2<<<J_, 128>>>(pp);
        int is_last = (it == NITER - 1);
        k_WT<<<I_, 128>>>(pp, is_last ? 0 : 1, is_last ? 1 : 0, out, nf, mode);
    }
}